// round 1
// baseline (speedup 1.0000x reference)
#include <cuda_runtime.h>
#include <cuda_bf16.h>
#include <math.h>

// Problem constants
#define B_  64
#define T_  32
#define D_  512
#define H_  1024
#define L_  4
#define G_  4096   // 4*H
#define OUT_ 1024

// ---------------- scratch (device globals; no allocation allowed) ----------
__device__ float g_R [4L * 64 * 4096];              // recurrent term per layer  [L][B][4H]
__device__ float g_Z [1984L * 4096];                // gate preactivations (max rows = 31*64)
__device__ float g_Hs[32L * 4 * 64 * 1024];         // all hidden outputs [T][L][B][H]
__device__ float g_Cc[4L * 64 * 1024];              // cs1 carries [L][B][H]

// ---------------- SGEMM: C[M,N] = A @ W + addRow[b(row)] + addBias ----------
// A row addressing: A + (row/64)*sT + (row%64)*sB   (lets us gather x[b,t,:] or
// g_Hs[t][l][b][:] without materializing a transposed copy)
// W is [K,N] row-major. C is [M,N] row-major contiguous.
#define BM 128
#define BN 128
#define BK 16

__global__ __launch_bounds__(256) void sgemm_kernel(
    const float* __restrict__ A, long sT, long sB,
    const float* __restrict__ W,
    float* __restrict__ C,
    const float* __restrict__ addRow,   // [64, N] or null (added per row%64)
    const float* __restrict__ addBias,  // [N] or null
    int M, int N, int K)
{
    __shared__ float As[BK][BM];
    __shared__ float Bs[BK][BN];

    const int tid = threadIdx.x;
    const int bm = blockIdx.y * BM;
    const int bn = blockIdx.x * BN;

    const int ty = tid >> 4;   // 0..15
    const int tx = tid & 15;   // 0..15

    float acc[8][8];
#pragma unroll
    for (int i = 0; i < 8; i++)
#pragma unroll
        for (int j = 0; j < 8; j++) acc[i][j] = 0.f;

    for (int k0 = 0; k0 < K; k0 += BK) {
        // --- load A tile (BM x BK) as float4, store transposed ---
#pragma unroll
        for (int it = 0; it < 2; it++) {
            int idx  = tid + it * 256;          // 0..511
            int arow = idx >> 2;                // 0..127
            int ak   = (idx & 3) * 4;           // 0,4,8,12
            int grow = bm + arow;
            float4 v;
            if (grow < M) {
                const float* ap = A + (long)(grow >> 6) * sT + (long)(grow & 63) * sB + k0 + ak;
                v = *(const float4*)ap;
            } else {
                v = make_float4(0.f, 0.f, 0.f, 0.f);
            }
            As[ak + 0][arow] = v.x;
            As[ak + 1][arow] = v.y;
            As[ak + 2][arow] = v.z;
            As[ak + 3][arow] = v.w;
        }
        // --- load B tile (BK x BN) coalesced float4 ---
#pragma unroll
        for (int it = 0; it < 2; it++) {
            int idx = tid + it * 256;           // 0..511
            int bk  = idx >> 5;                 // 0..15
            int bn4 = (idx & 31) * 4;           // 0..124
            float4 v = *(const float4*)(W + (long)(k0 + bk) * N + bn + bn4);
            *(float4*)&Bs[bk][bn4] = v;
        }
        __syncthreads();

#pragma unroll
        for (int k = 0; k < BK; k++) {
            float ar[8], br[8];
#pragma unroll
            for (int i = 0; i < 8; i++) ar[i] = As[k][ty * 8 + i];
#pragma unroll
            for (int j = 0; j < 8; j++) br[j] = Bs[k][tx * 8 + j];
#pragma unroll
            for (int i = 0; i < 8; i++)
#pragma unroll
                for (int j = 0; j < 8; j++)
                    acc[i][j] = fmaf(ar[i], br[j], acc[i][j]);
        }
        __syncthreads();
    }

    // --- epilogue: + addRow[row%64] + addBias, vectorized stores ---
#pragma unroll
    for (int i = 0; i < 8; i++) {
        int grow = bm + ty * 8 + i;
        if (grow >= M) continue;
        int b64 = grow & 63;
#pragma unroll
        for (int j4 = 0; j4 < 8; j4 += 4) {
            int gcol = bn + tx * 8 + j4;
            float4 r = make_float4(acc[i][j4], acc[i][j4 + 1], acc[i][j4 + 2], acc[i][j4 + 3]);
            if (addRow) {
                float4 a = *(const float4*)(addRow + (long)b64 * N + gcol);
                r.x += a.x; r.y += a.y; r.z += a.z; r.w += a.w;
            }
            if (addBias) {
                float4 a = *(const float4*)(addBias + gcol);
                r.x += a.x; r.y += a.y; r.z += a.z; r.w += a.w;
            }
            *(float4*)(C + (long)grow * N + gcol) = r;
        }
    }
}

// ---------------- LSTM gate nonlinearity --------------------------------
// Z: [rows, 4096]; carry c: [64, 1024] indexed by b=row%64
// h written to hbase + (row/64)*hStrideT + (row%64)*1024 + h
__global__ void gates_kernel(const float* __restrict__ Z,
                             const float* __restrict__ cc,
                             float* __restrict__ hbase, long hStrideT,
                             float* __restrict__ cout,
                             int rows)
{
    int idx = blockIdx.x * blockDim.x + threadIdx.x;
    if (idx >= rows * H_) return;
    int row = idx >> 10;
    int h   = idx & 1023;
    int b   = row & 63;
    int t   = row >> 6;
    const float* zr = Z + (long)row * G_;
    float zi = zr[h];
    float zf = zr[H_ + h];
    float zg = zr[2 * H_ + h];
    float zo = zr[3 * H_ + h];
    float cold = cc[(b << 10) + h];
    float si = 1.f / (1.f + expf(-zi));
    float sf = 1.f / (1.f + expf(-zf));
    float so = 1.f / (1.f + expf(-zo));
    float cn = sf * cold + si * tanhf(zg);
    float hn = so * tanhf(cn);
    hbase[t * hStrideT + (b << 10) + h] = hn;
    if (cout) cout[(b << 10) + h] = cn;
}

// ---------------- host driver ------------------------------------------
static inline void launch_gemm(const float* A, long sT, long sB,
                               const float* W, float* C,
                               const float* addRow, const float* addBias,
                               int M, int N, int K)
{
    dim3 grid(N / BN, (M + BM - 1) / BM);
    sgemm_kernel<<<grid, 256>>>(A, sT, sB, W, C, addRow, addBias, M, N, K);
}

static inline void launch_gates(const float* Z, const float* cc,
                                float* hbase, long hStrideT, float* cout, int rows)
{
    int total = rows * H_;
    gates_kernel<<<(total + 255) / 256, 256>>>(Z, cc, hbase, hStrideT, cout, rows);
}

extern "C" void kernel_launch(void* const* d_in, const int* in_sizes, int n_in,
                              void* d_out, int out_size)
{
    const float* x       = (const float*)d_in[0];  // [B,T,D]
    const float* Wx0     = (const float*)d_in[1];  // [D,4H]
    const float* Wx_rest = (const float*)d_in[2];  // [L-1,H,4H]
    const float* Wh      = (const float*)d_in[3];  // [L,H,4H]
    const float* bias    = (const float*)d_in[4];  // [L,4H]
    const float* Wd      = (const float*)d_in[5];  // [H,OUT]
    const float* bd      = (const float*)d_in[6];  // [OUT]
    const float* h0      = (const float*)d_in[7];  // [L,B,H]
    const float* c0      = (const float*)d_in[8];  // [L,B,H]
    float* out = (float*)d_out;                    // [T,L,B,OUT]

    float *pR, *pZ, *pH, *pCc;
    cudaGetSymbolAddress((void**)&pR,  g_R);
    cudaGetSymbolAddress((void**)&pZ,  g_Z);
    cudaGetSymbolAddress((void**)&pH,  g_Hs);
    cudaGetSymbolAddress((void**)&pCc, g_Cc);

    const long LBH = (long)L_ * B_ * H_;   // stride of one timestep in g_Hs
    const long BH  = (long)B_ * H_;
    const long BG  = (long)B_ * G_;
    const long HG  = (long)H_ * G_;

    // ---- Phase 1: R0[l] = h0[l] @ Wh[l] + b[l] ----
    for (int l = 0; l < L_; l++)
        launch_gemm(h0 + l * BH, BH, H_, Wh + (long)l * HG, pR + (long)l * BG,
                    nullptr, bias + (long)l * G_, B_, G_, H_);

    // ---- Phase 2: step 0 (sequential over layers) ----
    // layer 0: Z = x[:,0,:] @ Wx0 + R0[0]
    launch_gemm(x, D_, (long)T_ * D_, Wx0, pZ, pR, nullptr, B_, G_, D_);
    launch_gates(pZ, c0, pH, LBH, pCc, B_);   // h -> g_Hs[0][0], c -> cs1[0]
    for (int l = 1; l < L_; l++) {
        launch_gemm(pH + (long)(l - 1) * BH, BH, H_,
                    Wx_rest + (long)(l - 1) * HG, pZ,
                    pR + (long)l * BG, nullptr, B_, G_, H_);
        launch_gates(pZ, c0 + (long)l * BH, pH + (long)l * BH, LBH,
                     pCc + (long)l * BH, B_);
    }

    // ---- Phase 3: R1[l] = hs1[l] @ Wh[l] + b[l]  (hs1[l] == g_Hs[0][l]) ----
    for (int l = 0; l < L_; l++)
        launch_gemm(pH + (long)l * BH, BH, H_, Wh + (long)l * HG, pR + (long)l * BG,
                    nullptr, bias + (long)l * G_, B_, G_, H_);

    // ---- Phase 4: batched t = 1..31 (M = 31*64 = 1984) ----
    const int Mb = (T_ - 1) * B_;
    // layer 0: Z = x[:,1:,:] @ Wx0 + R1[0]
    launch_gemm(x + D_, D_, (long)T_ * D_, Wx0, pZ, pR, nullptr, Mb, G_, D_);
    launch_gates(pZ, pCc, pH + LBH, LBH, nullptr, Mb);    // h -> g_Hs[1..31][0]
    for (int l = 1; l < L_; l++) {
        launch_gemm(pH + LBH + (long)(l - 1) * BH, LBH, H_,
                    Wx_rest + (long)(l - 1) * HG, pZ,
                    pR + (long)l * BG, nullptr, Mb, G_, H_);
        launch_gates(pZ, pCc + (long)l * BH, pH + LBH + (long)l * BH, LBH,
                     nullptr, Mb);
    }

    // ---- Phase 5: out[t][l][b][:] = g_Hs[t][l][b][:] @ Wd + bd  (one big GEMM) ----
    launch_gemm(pH, BH, H_, Wd, out, nullptr, bd, T_ * L_ * B_, OUT_, H_);
}

// round 2
// speedup vs baseline: 3.4349x; 3.4349x over previous
#include <cuda_runtime.h>
#include <cuda_bf16.h>
#include <math.h>
#include <stdint.h>

// Problem constants
#define B_   64
#define T_   32
#define D_   512
#define H_   1024
#define L_   4
#define G_   4096   // 4*H
#define OUT_ 1024

// ---------------- device scratch (no allocation allowed) -------------------
// bf16 hi/lo splits of weights
__device__ __nv_bfloat16 g_Wx0h[512L*4096], g_Wx0l[512L*4096];
__device__ __nv_bfloat16 g_Wxrh[3L*1024*4096], g_Wxrl[3L*1024*4096];
__device__ __nv_bfloat16 g_Whh [4L*1024*4096], g_Whl [4L*1024*4096];
__device__ __nv_bfloat16 g_Wdh [1024L*1024],   g_Wdl [1024L*1024];
// activations
__device__ __nv_bfloat16 g_xsh[2048L*512], g_xsl[2048L*512];      // x rows r=(t<<6)|b
__device__ __nv_bfloat16 g_h0h[4L*64*1024], g_h0l[4L*64*1024];    // h0 split
__device__ __nv_bfloat16 g_hh [32L*4*64*1024], g_hl[32L*4*64*1024]; // h splits [t][l][b][h]
// fp32 scratch
__device__ float g_Z [2048L*4096];          // gate preactivations
__device__ float g_R [4L*64*4096];          // recurrent addend per layer
__device__ float g_P [4L*4*64*4096];        // split-K partials [layer][split][64][4096]
__device__ float g_Cc[4L*64*1024];          // cs1 carries

// ---------------- PTX helpers ---------------------------------------------
__device__ __forceinline__ uint32_t s2u(const void* p) {
    return (uint32_t)__cvta_generic_to_shared(p);
}
__device__ __forceinline__ void cpa16(uint32_t dst, const void* src) {
    asm volatile("cp.async.cg.shared.global [%0], [%1], 16;\n" :: "r"(dst), "l"(src));
}
__device__ __forceinline__ void cp_commit() { asm volatile("cp.async.commit_group;\n"); }
template<int N_> __device__ __forceinline__ void cp_wait() {
    asm volatile("cp.async.wait_group %0;\n" :: "n"(N_));
}
__device__ __forceinline__ void ldsm_x4(uint32_t a, uint32_t r[4]) {
    asm volatile("ldmatrix.sync.aligned.m8n8.x4.shared.b16 {%0,%1,%2,%3}, [%4];\n"
                 : "=r"(r[0]), "=r"(r[1]), "=r"(r[2]), "=r"(r[3]) : "r"(a));
}
__device__ __forceinline__ void ldsm_x2t(uint32_t a, uint32_t r[2]) {
    asm volatile("ldmatrix.sync.aligned.m8n8.x2.trans.shared.b16 {%0,%1}, [%2];\n"
                 : "=r"(r[0]), "=r"(r[1]) : "r"(a));
}
__device__ __forceinline__ void mma16816(float c[4], const uint32_t a[4], const uint32_t b[2]) {
    asm volatile(
        "mma.sync.aligned.m16n8k16.row.col.f32.bf16.bf16.f32 "
        "{%0,%1,%2,%3}, {%4,%5,%6,%7}, {%8,%9}, {%0,%1,%2,%3};\n"
        : "+f"(c[0]), "+f"(c[1]), "+f"(c[2]), "+f"(c[3])
        : "r"(a[0]), "r"(a[1]), "r"(a[2]), "r"(a[3]), "r"(b[0]), "r"(b[1]));
}

// ---------------- split kernels --------------------------------------------
__global__ void split_kernel(const float* __restrict__ src,
                             __nv_bfloat16* __restrict__ hi,
                             __nv_bfloat16* __restrict__ lo, long n) {
    long i = (long)blockIdx.x * blockDim.x + threadIdx.x;
    long stride = (long)gridDim.x * blockDim.x;
    for (; i < n; i += stride) {
        float v = src[i];
        __nv_bfloat16 h = __float2bfloat16(v);
        float r = v - __bfloat162float(h);
        hi[i] = h;
        lo[i] = __float2bfloat16(r);
    }
}

// x [B,T,D] -> xs rows r=(t<<6)|b, [2048][512]
__global__ void splitx_kernel(const float* __restrict__ x,
                              __nv_bfloat16* __restrict__ hi,
                              __nv_bfloat16* __restrict__ lo) {
    int idx = blockIdx.x * blockDim.x + threadIdx.x;
    if (idx >= 2048 * 512) return;
    int r = idx >> 9, d = idx & 511;
    int t = r >> 6, b = r & 63;
    float v = x[((long)b * 32 + t) * 512 + d];
    __nv_bfloat16 h = __float2bfloat16(v);
    hi[idx] = h;
    lo[idx] = __float2bfloat16(v - __bfloat162float(h));
}

// ---------------- big GEMM: 128x128x32, bf16x3, double-buffered ------------
// C[M,N] = (Ah+Al) @ (Wh+Wl) [+ addRow[row&63]] [+ addBias]
// A row r addressed as base + (r>>6)*sT + (r&63)*sB (element offsets)
// M = gridDim.y*128 (always exact multiple), N % 128 == 0, K % 32 == 0.
// smem layout (bytes): Ah[2][128][40]@0 (10240/buf), Al@20480,
//                      Bh[2][32][136]@40960 (8704/buf), Bl@58368. total 75776.
__global__ __launch_bounds__(256) void gemm_big(
    const __nv_bfloat16* __restrict__ Ah, const __nv_bfloat16* __restrict__ Al,
    long sT, long sB,
    const __nv_bfloat16* __restrict__ Wh, const __nv_bfloat16* __restrict__ Wl,
    float* __restrict__ C,
    const float* __restrict__ addRow, const float* __restrict__ addBias,
    int N, int K)
{
    extern __shared__ __align__(16) unsigned char smraw[];
    const uint32_t sbase = s2u(smraw);
    const int tid = threadIdx.x;
    const int bm = blockIdx.y * 128, bn = blockIdx.x * 128;

    const int warp = tid >> 5, lane = tid & 31;
    const int wm = warp >> 2, wn = warp & 3;
    const int q = lane >> 3, rr = lane & 7;
    const int arow = rr + (q & 1) * 8;
    const int acol = (q >> 1) * 8;
    const int brow = lane & 15;

    float acc[4][4][4];
#pragma unroll
    for (int i = 0; i < 4; i++)
#pragma unroll
        for (int j = 0; j < 4; j++)
#pragma unroll
            for (int k = 0; k < 4; k++) acc[i][j][k] = 0.f;

    auto load_stage = [&](int kt, int buf) {
        int k0 = kt * 32;
#pragma unroll
        for (int it = 0; it < 2; it++) {
            int i = tid + it * 256;          // 0..511
            int row = i >> 2, ch = i & 3;
            int gr = bm + row;
            long off = (long)(gr >> 6) * sT + (long)(gr & 63) * sB + k0 + ch * 8;
            uint32_t d = sbase + (uint32_t)buf * 10240u + (uint32_t)row * 80u + (uint32_t)ch * 16u;
            cpa16(d, Ah + off);
            cpa16(d + 20480u, Al + off);
        }
#pragma unroll
        for (int it = 0; it < 2; it++) {
            int i = tid + it * 256;          // 0..511
            int row = i >> 4, ch = i & 15;
            long off = (long)(k0 + row) * N + bn + ch * 8;
            uint32_t d = sbase + 40960u + (uint32_t)buf * 8704u + (uint32_t)row * 272u + (uint32_t)ch * 16u;
            cpa16(d, Wh + off);
            cpa16(d + 17408u, Wl + off);
        }
        cp_commit();
    };

    const int KT = K / 32;
    load_stage(0, 0);
    for (int kt = 0; kt < KT; kt++) {
        int buf = kt & 1;
        if (kt + 1 < KT) { load_stage(kt + 1, buf ^ 1); cp_wait<1>(); }
        else             { cp_wait<0>(); }
        __syncthreads();
#pragma unroll
        for (int ks = 0; ks < 2; ks++) {
            uint32_t ah[4][4], al[4][4], bh[4][2], bl[4][2];
#pragma unroll
            for (int mi = 0; mi < 4; mi++) {
                int m = wm * 64 + mi * 16 + arow;
                uint32_t a = sbase + (uint32_t)buf * 10240u + (uint32_t)m * 80u
                           + (uint32_t)(ks * 16 + acol) * 2u;
                ldsm_x4(a, ah[mi]);
                ldsm_x4(a + 20480u, al[mi]);
            }
#pragma unroll
            for (int ni = 0; ni < 4; ni++) {
                int n = wn * 32 + ni * 8;
                uint32_t a = sbase + 40960u + (uint32_t)buf * 8704u
                           + (uint32_t)(ks * 16 + brow) * 272u + (uint32_t)n * 2u;
                ldsm_x2t(a, bh[ni]);
                ldsm_x2t(a + 17408u, bl[ni]);
            }
#pragma unroll
            for (int mi = 0; mi < 4; mi++)
#pragma unroll
                for (int ni = 0; ni < 4; ni++) {
                    mma16816(acc[mi][ni], ah[mi], bh[ni]);
                    mma16816(acc[mi][ni], ah[mi], bl[ni]);
                    mma16816(acc[mi][ni], al[mi], bh[ni]);
                }
        }
        __syncthreads();
    }

    // epilogue
#pragma unroll
    for (int mi = 0; mi < 4; mi++)
#pragma unroll
        for (int ni = 0; ni < 4; ni++) {
            int row0 = bm + wm * 64 + mi * 16 + (lane >> 2);
            int col  = bn + wn * 32 + ni * 8 + (lane & 3) * 2;
#pragma unroll
            for (int hh = 0; hh < 2; hh++) {
                int row = row0 + hh * 8;
                float v0 = acc[mi][ni][hh * 2 + 0];
                float v1 = acc[mi][ni][hh * 2 + 1];
                if (addRow) {
                    const float* p = addRow + (long)(row & 63) * N + col;
                    v0 += p[0]; v1 += p[1];
                }
                if (addBias) { v0 += addBias[col]; v1 += addBias[col + 1]; }
                *(float2*)(C + (long)row * N + col) = make_float2(v0, v1);
            }
        }
}

// ---------------- small GEMM: M=64, N=4096, split-K -------------------------
// grid (N/64, layers, NS). Partials -> P[(layer*NS+split)][64][4096]
__global__ __launch_bounds__(128) void gemm_small(
    const __nv_bfloat16* __restrict__ Ah, const __nv_bfloat16* __restrict__ Al,
    long aLayer, int aRow,
    const __nv_bfloat16* __restrict__ Wh, const __nv_bfloat16* __restrict__ Wl,
    long wLayer,
    float* __restrict__ P, int K, int NS)
{
    __shared__ __align__(16) unsigned char smraw[19456];
    const uint32_t sbase = s2u(smraw);
    const int tid = threadIdx.x;
    const int l = blockIdx.y, z = blockIdx.z;
    const int bn = blockIdx.x * 64;
    const int Ks = K / NS;
    const int kbase = z * Ks;
    const int N = 4096;

    const int warp = tid >> 5, lane = tid & 31;
    const int q = lane >> 3, rr = lane & 7;
    const int arow = rr + (q & 1) * 8;
    const int acol = (q >> 1) * 8;
    const int brow = lane & 15;

    float acc[4][2][4];
#pragma unroll
    for (int i = 0; i < 4; i++)
#pragma unroll
        for (int j = 0; j < 2; j++)
#pragma unroll
            for (int k = 0; k < 4; k++) acc[i][j][k] = 0.f;

    const int KT = Ks / 32;
    for (int kt = 0; kt < KT; kt++) {
        int k0 = kbase + kt * 32;
        // A: 64 rows x 4 chunks x (hi,lo)
#pragma unroll
        for (int it = 0; it < 2; it++) {
            int i = tid + it * 128;            // 0..255
            int row = i >> 2, ch = i & 3;
            long off = (long)l * aLayer + (long)row * aRow + k0 + ch * 8;
            uint32_t d = sbase + (uint32_t)row * 80u + (uint32_t)ch * 16u;
            cpa16(d, Ah + off);
            cpa16(d + 5120u, Al + off);
        }
        // B: 32 rows x 8 chunks x (hi,lo)
#pragma unroll
        for (int it = 0; it < 2; it++) {
            int i = tid + it * 128;            // 0..255
            int row = i >> 3, ch = i & 7;
            long off = (long)l * wLayer + (long)(k0 + row) * N + bn + ch * 8;
            uint32_t d = sbase + 10240u + (uint32_t)row * 144u + (uint32_t)ch * 16u;
            cpa16(d, Wh + off);
            cpa16(d + 4608u, Wl + off);
        }
        cp_commit();
        cp_wait<0>();
        __syncthreads();
#pragma unroll
        for (int ks = 0; ks < 2; ks++) {
            uint32_t ah[4][4], al[4][4], bh[2][2], bl[2][2];
#pragma unroll
            for (int mi = 0; mi < 4; mi++) {
                int m = mi * 16 + arow;
                uint32_t a = sbase + (uint32_t)m * 80u + (uint32_t)(ks * 16 + acol) * 2u;
                ldsm_x4(a, ah[mi]);
                ldsm_x4(a + 5120u, al[mi]);
            }
#pragma unroll
            for (int ni = 0; ni < 2; ni++) {
                int n = warp * 16 + ni * 8;
                uint32_t a = sbase + 10240u + (uint32_t)(ks * 16 + brow) * 144u + (uint32_t)n * 2u;
                ldsm_x2t(a, bh[ni]);
                ldsm_x2t(a + 4608u, bl[ni]);
            }
#pragma unroll
            for (int mi = 0; mi < 4; mi++)
#pragma unroll
                for (int ni = 0; ni < 2; ni++) {
                    mma16816(acc[mi][ni], ah[mi], bh[ni]);
                    mma16816(acc[mi][ni], ah[mi], bl[ni]);
                    mma16816(acc[mi][ni], al[mi], bh[ni]);
                }
        }
        __syncthreads();
    }

    float* Pout = P + ((long)(l * NS + z) * 64) * 4096;
#pragma unroll
    for (int mi = 0; mi < 4; mi++)
#pragma unroll
        for (int ni = 0; ni < 2; ni++) {
            int row0 = mi * 16 + (lane >> 2);
            int col  = bn + warp * 16 + ni * 8 + (lane & 3) * 2;
#pragma unroll
            for (int hh = 0; hh < 2; hh++) {
                int row = row0 + hh * 8;
                *(float2*)(Pout + (long)row * 4096 + col) =
                    make_float2(acc[mi][ni][hh * 2], acc[mi][ni][hh * 2 + 1]);
            }
        }
}

// ---------------- reductions / gates ----------------------------------------
__global__ void reduce_R_kernel(const float* __restrict__ P,
                                const float* __restrict__ bias,
                                float* __restrict__ R) {
    int idx = blockIdx.x * blockDim.x + threadIdx.x;
    if (idx >= 4 * 64 * 4096) return;
    int l = idx >> 18;
    int rem = idx & 262143;
    int b = rem >> 12, n = rem & 4095;
    float s = bias[l * 4096 + n];
#pragma unroll
    for (int s4 = 0; s4 < 4; s4++)
        s += P[((long)(l * 4 + s4) * 64 + b) * 4096 + n];
    R[idx] = s;
}

__device__ __forceinline__ void gate_math(float zi, float zf, float zg, float zo,
                                          float cold, float& hn, float& cn) {
    float si = 1.f / (1.f + expf(-zi));
    float sf = 1.f / (1.f + expf(-zf));
    float so = 1.f / (1.f + expf(-zo));
    cn = sf * cold + si * tanhf(zg);
    hn = so * tanhf(cn);
}

// phase 2: sum partials + R0[l] -> gates -> h split at [t=0][l], c -> Cc[l]
__global__ void reduce_gates_kernel(const float* __restrict__ P,
                                    const float* __restrict__ R,
                                    const float* __restrict__ c0,
                                    int l,
                                    __nv_bfloat16* __restrict__ hh,
                                    __nv_bfloat16* __restrict__ hl,
                                    float* __restrict__ Cc) {
    int idx = blockIdx.x * blockDim.x + threadIdx.x;
    if (idx >= 64 * 1024) return;
    int b = idx >> 10, h = idx & 1023;
    float zg4[4];
#pragma unroll
    for (int g = 0; g < 4; g++) {
        int n = g * 1024 + h;
        float s = R[(long)l * 262144 + (long)b * 4096 + n];
#pragma unroll
        for (int s4 = 0; s4 < 4; s4++)
            s += P[((long)s4 * 64 + b) * 4096 + n];
        zg4[g] = s;
    }
    float cold = c0[(long)l * 65536 + idx];
    float hn, cn;
    gate_math(zg4[0], zg4[1], zg4[2], zg4[3], cold, hn, cn);
    long off = (long)l * 65536 + idx;       // t=0 slot
    __nv_bfloat16 hhi = __float2bfloat16(hn);
    hh[off] = hhi;
    hl[off] = __float2bfloat16(hn - __bfloat162float(hhi));
    Cc[(long)l * 65536 + idx] = cn;
}

// phase 4: Z rows 64..2047 -> gates with frozen carry -> h split t=1..31 layer l
__global__ void gates_big_kernel(const float* __restrict__ Z,
                                 const float* __restrict__ Cc,  // Cc + l*65536
                                 __nv_bfloat16* __restrict__ hh,
                                 __nv_bfloat16* __restrict__ hl,
                                 int l) {
    int idx = blockIdx.x * blockDim.x + threadIdx.x;
    if (idx >= 1984 * 1024) return;
    int row = (idx >> 10) + 64;     // global Z row, t>=1
    int h = idx & 1023;
    int t = row >> 6, b = row & 63;
    const float* zr = Z + (long)row * 4096;
    float cold = Cc[(long)b * 1024 + h];
    float hn, cn;
    gate_math(zr[h], zr[1024 + h], zr[2048 + h], zr[3072 + h], cold, hn, cn);
    long off = (long)t * 262144 + (long)l * 65536 + (long)b * 1024 + h;
    __nv_bfloat16 hhi = __float2bfloat16(hn);
    hh[off] = hhi;
    hl[off] = __float2bfloat16(hn - __bfloat162float(hhi));
}

// ---------------- host driver ------------------------------------------
extern "C" void kernel_launch(void* const* d_in, const int* in_sizes, int n_in,
                              void* d_out, int out_size)
{
    const float* x       = (const float*)d_in[0];
    const float* Wx0     = (const float*)d_in[1];
    const float* Wx_rest = (const float*)d_in[2];
    const float* Wh      = (const float*)d_in[3];
    const float* bias    = (const float*)d_in[4];
    const float* Wd      = (const float*)d_in[5];
    const float* bd      = (const float*)d_in[6];
    const float* h0      = (const float*)d_in[7];
    const float* c0      = (const float*)d_in[8];
    float* out = (float*)d_out;

    __nv_bfloat16 *wx0h, *wx0l, *wxrh, *wxrl, *whh, *whl, *wdh, *wdl;
    __nv_bfloat16 *xsh, *xsl, *h0h, *h0l, *hh, *hl;
    float *pZ, *pR, *pP, *pCc;
    cudaGetSymbolAddress((void**)&wx0h, g_Wx0h); cudaGetSymbolAddress((void**)&wx0l, g_Wx0l);
    cudaGetSymbolAddress((void**)&wxrh, g_Wxrh); cudaGetSymbolAddress((void**)&wxrl, g_Wxrl);
    cudaGetSymbolAddress((void**)&whh,  g_Whh);  cudaGetSymbolAddress((void**)&whl,  g_Whl);
    cudaGetSymbolAddress((void**)&wdh,  g_Wdh);  cudaGetSymbolAddress((void**)&wdl,  g_Wdl);
    cudaGetSymbolAddress((void**)&xsh,  g_xsh);  cudaGetSymbolAddress((void**)&xsl,  g_xsl);
    cudaGetSymbolAddress((void**)&h0h,  g_h0h);  cudaGetSymbolAddress((void**)&h0l,  g_h0l);
    cudaGetSymbolAddress((void**)&hh,   g_hh);   cudaGetSymbolAddress((void**)&hl,   g_hl);
    cudaGetSymbolAddress((void**)&pZ,   g_Z);    cudaGetSymbolAddress((void**)&pR,   g_R);
    cudaGetSymbolAddress((void**)&pP,   g_P);    cudaGetSymbolAddress((void**)&pCc,  g_Cc);

    cudaFuncSetAttribute(gemm_big, cudaFuncAttributeMaxDynamicSharedMemorySize, 75776);

    const long BH = 64L * 1024;       // 65536
    const long HG = 1024L * 4096;     // weight layer stride
    const long LBH = 4L * BH;         // 262144, t stride in g_hh

    // ---- splits ----
    split_kernel<<<2048, 256>>>(Wx0,     wx0h, wx0l, 512L * 4096);
    split_kernel<<<8192, 256>>>(Wx_rest, wxrh, wxrl, 3L * 1024 * 4096);
    split_kernel<<<8192, 256>>>(Wh,      whh,  whl,  4L * 1024 * 4096);
    split_kernel<<<2048, 256>>>(Wd,      wdh,  wdl,  1024L * 1024);
    split_kernel<<<1024, 256>>>(h0,      h0h,  h0l,  4L * 64 * 1024);
    splitx_kernel<<<(2048 * 512) / 256, 256>>>(x, xsh, xsl);

    // ---- Phase 1: R0[l] = h0[l] @ Wh[l] + b[l]  (batched over l, split-K=4) ----
    {
        dim3 g(64, 4, 4);
        gemm_small<<<g, 128>>>(h0h, h0l, BH, 1024, whh, whl, HG, pP, 1024, 4);
        reduce_R_kernel<<<(4 * 64 * 4096) / 256, 256>>>(pP, bias, pR);
    }

    // ---- Phase 2: step 0, sequential over layers ----
    {
        dim3 g(64, 1, 4);
        // layer 0: A = xs rows 0..63 (t=0), K=512
        gemm_small<<<g, 128>>>(xsh, xsl, 0, 512, wx0h, wx0l, 0, pP, 512, 4);
        reduce_gates_kernel<<<256, 256>>>(pP, pR, c0, 0, hh, hl, pCc);
        for (int l = 1; l < L_; l++) {
            gemm_small<<<g, 128>>>(hh + (l - 1) * BH, hl + (l - 1) * BH, 0, 1024,
                                   wxrh + (long)(l - 1) * HG, wxrl + (long)(l - 1) * HG, 0,
                                   pP, 1024, 4);
            reduce_gates_kernel<<<256, 256>>>(pP, pR, c0, l, hh, hl, pCc);
        }
    }

    // ---- Phase 3: R1[l] = hs1[l] @ Wh[l] + b[l]  (hs1 = h split at t=0) ----
    {
        dim3 g(64, 4, 4);
        gemm_small<<<g, 128>>>(hh, hl, BH, 1024, whh, whl, HG, pP, 1024, 4);
        reduce_R_kernel<<<(4 * 64 * 4096) / 256, 256>>>(pP, bias, pR);
    }

    // ---- Phase 4: batched t (M padded to 2048, t=0 rows computed but ignored) ----
    {
        dim3 g0(32, 16);  // N=4096/128, M=2048/128
        // layer 0: A = xs (all 2048 rows), K=512
        gemm_big<<<g0, 256, 75776>>>(xsh, xsl, 64L * 512, 512,
                                     wx0h, wx0l, pZ, pR, nullptr, 4096, 512);
        gates_big_kernel<<<(1984 * 1024) / 256, 256>>>(pZ, pCc, hh, hl, 0);
        for (int l = 1; l < L_; l++) {
            gemm_big<<<g0, 256, 75776>>>(hh + (l - 1) * BH, hl + (l - 1) * BH,
                                         LBH, 1024,
                                         wxrh + (long)(l - 1) * HG, wxrl + (long)(l - 1) * HG,
                                         pZ, pR + (long)l * 64 * 4096, nullptr, 4096, 1024);
            gates_big_kernel<<<(1984 * 1024) / 256, 256>>>(pZ, pCc + (long)l * BH, hh, hl, l);
        }
    }

    // ---- Phase 5: out = h @ Wd + bd, one GEMM M=8192 ----
    {
        dim3 g(8, 64);   // N=1024/128, M=8192/128
        gemm_big<<<g, 256, 75776>>>(hh, hl, BH, 1024, wdh, wdl,
                                    out, nullptr, bd, 1024, 1024);
    }
}